// round 15
// baseline (speedup 1.0000x reference)
#include <cuda_runtime.h>
#include <cuda_fp16.h>
#include <cstdint>

#define D_MODEL  1024
#define D_STATE  128
#define D_INNER  2048
#define HEADS    1024
#define PROJ_OUT 5376
#define BATCH    2
#define SEQ      2048
#define NTOK     (BATCH*SEQ)   // 4096

// ---------------- scratch (device globals) -----------------------------------
__device__ float g_x    [(size_t)NTOK * D_INNER];   // x columns (pre-conv)
__device__ float g_zsil [(size_t)NTOK * D_INNER];   // silu(z)
__device__ float g_B    [(size_t)NTOK * D_STATE];
__device__ float g_C    [(size_t)NTOK * D_STATE];
__device__ float g_dtp  [(size_t)NTOK * HEADS];     // softplus(dt)
__device__ float g_decay[(size_t)NTOK * HEADS];     // exp(dtp * -exp(A_log))
__device__ float g_dtx  [(size_t)NTOK * D_INNER];   // dtp * silu(conv(x))
__device__ __half g_Ain [(size_t)NTOK * D_MODEL];      // fp16(ln(u))
__device__ __half g_Bin [(size_t)PROJ_OUT * D_MODEL];  // fp16(W_in^T)
__device__ __half g_Ay  [(size_t)NTOK * D_INNER];      // fp16(y*silu(z))
__device__ __half g_Bout[(size_t)D_MODEL * D_INNER];   // fp16(W_out^T)

// ---------------- helpers -----------------------------------------------------
struct alignas(8) hf4 { __half v[4]; };

__device__ __forceinline__ uint32_t smem_u32(const void* p) {
    uint32_t a;
    asm("{ .reg .u64 t; cvta.to.shared.u64 t, %1; cvt.u32.u64 %0, t; }" : "=r"(a) : "l"(p));
    return a;
}
__device__ __forceinline__ void cp16(uint32_t s, const void* g) {
    asm volatile("cp.async.cg.shared.global [%0], [%1], 16;" :: "r"(s), "l"(g) : "memory");
}
#define CP_COMMIT() asm volatile("cp.async.commit_group;" ::: "memory")

__device__ __forceinline__ void ldsm_x4(uint32_t& r0, uint32_t& r1, uint32_t& r2, uint32_t& r3,
                                        uint32_t addr) {
    asm volatile("ldmatrix.sync.aligned.m8n8.x4.shared.b16 {%0,%1,%2,%3}, [%4];"
                 : "=r"(r0), "=r"(r1), "=r"(r2), "=r"(r3) : "r"(addr));
}
__device__ __forceinline__ void mma16816(float& d0, float& d1, float& d2, float& d3,
                                         uint32_t a0, uint32_t a1, uint32_t a2, uint32_t a3,
                                         uint32_t b0, uint32_t b1) {
    asm volatile("mma.sync.aligned.m16n8k16.row.col.f32.f16.f16.f32 "
                 "{%0,%1,%2,%3}, {%4,%5,%6,%7}, {%8,%9}, {%0,%1,%2,%3};"
                 : "+f"(d0), "+f"(d1), "+f"(d2), "+f"(d3)
                 : "r"(a0), "r"(a1), "r"(a2), "r"(a3), "r"(b0), "r"(b1));
}
// smem tile byte offset, row-major [rows][32] fp16 with XOR swizzle for LDSM
__device__ __forceinline__ uint32_t swz(uint32_t row, uint32_t k) {
    uint32_t chunk = (k >> 3) ^ ((row >> 1) & 3);
    return row * 64 + chunk * 16 + (k & 7) * 2;
}
__device__ __forceinline__ float sp_(float v) {           // softplus
    return (v > 20.f) ? v : log1pf(expf(v));
}
__device__ __forceinline__ float silu_(float v) {
    return v / (1.f + expf(-v));
}

// ---------------- 1. LayerNorm -> fp16 A --------------------------------------
__global__ void __launch_bounds__(256) ln_kernel(const float* __restrict__ u,
                                                 const float* __restrict__ g,
                                                 const float* __restrict__ b) {
    __shared__ float sS[8], sQ[8], sMV[2];
    const int row = blockIdx.x;
    const int tid = threadIdx.x;
    const int warp = tid >> 5, lane = tid & 31;

    float4 v = *((const float4*)(u + (size_t)row * D_MODEL) + tid);
    float s = v.x + v.y + v.z + v.w;
    float q = v.x*v.x + v.y*v.y + v.z*v.z + v.w*v.w;
    #pragma unroll
    for (int off = 16; off > 0; off >>= 1) {
        s += __shfl_xor_sync(0xffffffffu, s, off);
        q += __shfl_xor_sync(0xffffffffu, q, off);
    }
    if (lane == 0) { sS[warp] = s; sQ[warp] = q; }
    __syncthreads();
    if (tid == 0) {
        float S = 0.f, Q = 0.f;
        #pragma unroll
        for (int i = 0; i < 8; ++i) { S += sS[i]; Q += sQ[i]; }
        float mean = S * (1.0f / D_MODEL);
        float var  = Q * (1.0f / D_MODEL) - mean * mean;
        sMV[0] = mean;
        sMV[1] = rsqrtf(var + 1e-5f);
    }
    __syncthreads();
    const float mean = sMV[0], rstd = sMV[1];
    float4 gg = ((const float4*)g)[tid];
    float4 bb = ((const float4*)b)[tid];
    hf4 H;
    H.v[0] = __float2half_rn((v.x - mean) * rstd * gg.x + bb.x);
    H.v[1] = __float2half_rn((v.y - mean) * rstd * gg.y + bb.y);
    H.v[2] = __float2half_rn((v.z - mean) * rstd * gg.z + bb.z);
    H.v[3] = __float2half_rn((v.w - mean) * rstd * gg.w + bb.w);
    *(hf4*)(g_Ain + (size_t)row * D_MODEL + tid * 4) = H;
}

// ---------------- weight transpose fp16: W[K,N] -> B[N,K] --------------------
template<int PHASE>
__global__ void wconv_kernel(const float* __restrict__ W) {
    constexpr int K = PHASE ? D_INNER : D_MODEL;
    constexpr int N = PHASE ? D_MODEL : PROJ_OUT;
    __half* __restrict__ Bo = PHASE ? g_Bout : g_Bin;

    __shared__ float t[32][33];
    const int tx = threadIdx.x, ty = threadIdx.y;
    const int n0 = blockIdx.x * 32, k0 = blockIdx.y * 32;
    t[ty][tx] = W[(size_t)(k0 + ty) * N + n0 + tx];
    __syncthreads();
    Bo[(size_t)(n0 + ty) * K + k0 + tx] = __float2half_rn(t[tx][ty]);
}

// ---------------- fp16 mma.sync GEMM (256x128x32, 3-stage, ldmatrix) ---------
// warp grid 4x2, warp tile 64x64 (acc[4][8][4]).
// PHASE 0: g_Ain @ g_Bin^T  -> fused segment epilogue (compact buffers)
// PHASE 1: g_Ay @ g_Bout^T + u -> out fp32
#define STAGEB 24576
#define GEMM_SMEM (3 * STAGEB)   // 72 KB dynamic
template<int PHASE>
__global__ void __launch_bounds__(256, 1) gemm_mma(const float* __restrict__ R,
                                                   float* __restrict__ Cout,
                                                   const float* __restrict__ A_log) {
    constexpr int TK = PHASE ? D_INNER : D_MODEL;
    constexpr int NC = PHASE ? D_MODEL : PROJ_OUT;
    constexpr int NITER = TK / 32;

    const __half* Asrc = PHASE ? g_Ay  : g_Ain;
    const __half* Bsrc = PHASE ? g_Bout : g_Bin;

    extern __shared__ char smemraw[];
    const uint32_t sb = smem_u32(smemraw);

    const int tid = threadIdx.x;
    const int wid = tid >> 5, lane = tid & 31;
    const int wm = wid & 3, wn = wid >> 2;          // 4x2 warps, tile 64x64
    const int m0 = blockIdx.y * 256, n0 = blockIdx.x * 128;
    const __half* Ag = Asrc + (size_t)m0 * TK;
    const __half* Bg = Bsrc + (size_t)n0 * TK;

    auto load_stage = [&](int it, int st) {
        const int k0 = it * 32;
        const uint32_t base = sb + st * STAGEB;
        #pragma unroll
        for (int i = 0; i < 6; ++i) {
            const int idx = tid + i * 256;          // 0..1535: [0,1024)=A, rest=B
            if (idx < 1024) {
                const int row = idx >> 2, ch = idx & 3;
                cp16(base + swz(row, ch * 8), Ag + (size_t)row * TK + k0 + ch * 8);
            } else {
                const int w = idx - 1024;
                const int row = w >> 2, ch = w & 3;
                cp16(base + 16384 + swz(row, ch * 8), Bg + (size_t)row * TK + k0 + ch * 8);
            }
        }
    };

    float acc[4][8][4];
    #pragma unroll
    for (int mt = 0; mt < 4; ++mt)
        #pragma unroll
        for (int nt = 0; nt < 8; ++nt)
            #pragma unroll
            for (int r = 0; r < 4; ++r) acc[mt][nt][r] = 0.f;

    load_stage(0, 0); CP_COMMIT();
    load_stage(1, 1); CP_COMMIT();

    const uint32_t a_row = wm * 64 + (lane & 15);
    const uint32_t a_k   = (lane >> 4) * 8;
    const uint32_t b_row = wn * 64 + ((lane >> 4) & 1) * 8 + (lane & 7);
    const uint32_t b_k   = ((lane >> 3) & 1) * 8;

    int st = 0;
    for (int it = 0; it < NITER; ++it) {
        asm volatile("cp.async.wait_group 1;" ::: "memory");
        __syncthreads();
        if (it + 2 < NITER) load_stage(it + 2, (st + 2) % 3);
        CP_COMMIT();

        const uint32_t abase = sb + st * STAGEB;
        const uint32_t bbase = abase + 16384;
        #pragma unroll
        for (int ks = 0; ks < 2; ++ks) {
            uint32_t a[4][4], b[8][2];
            #pragma unroll
            for (int mt = 0; mt < 4; ++mt)
                ldsm_x4(a[mt][0], a[mt][1], a[mt][2], a[mt][3],
                        abase + swz(a_row + mt * 16, ks * 16 + a_k));
            #pragma unroll
            for (int nt2 = 0; nt2 < 4; ++nt2)
                ldsm_x4(b[nt2*2][0], b[nt2*2][1], b[nt2*2+1][0], b[nt2*2+1][1],
                        bbase + swz(b_row + nt2 * 16, ks * 16 + b_k));
            #pragma unroll
            for (int mt = 0; mt < 4; ++mt)
                #pragma unroll
                for (int nt = 0; nt < 8; ++nt)
                    mma16816(acc[mt][nt][0], acc[mt][nt][1], acc[mt][nt][2], acc[mt][nt][3],
                             a[mt][0], a[mt][1], a[mt][2], a[mt][3], b[nt][0], b[nt][1]);
        }
        st = (st + 1) % 3;
    }

    const int rbase = m0 + wm * 64 + (lane >> 2);
    const int cbase = n0 + wn * 64 + 2 * (lane & 3);

    if (PHASE == 1) {
        #pragma unroll
        for (int mt = 0; mt < 4; ++mt)
            #pragma unroll
            for (int nt = 0; nt < 8; ++nt) {
                const int rr0 = rbase + mt * 16;
                const int cc  = cbase + nt * 8;
                float2 v0 = make_float2(acc[mt][nt][0], acc[mt][nt][1]);
                float2 v1 = make_float2(acc[mt][nt][2], acc[mt][nt][3]);
                float2 r0 = *(const float2*)&R[(size_t)rr0 * NC + cc];
                float2 r1 = *(const float2*)&R[(size_t)(rr0 + 8) * NC + cc];
                v0.x += r0.x; v0.y += r0.y;
                v1.x += r1.x; v1.y += r1.y;
                *(float2*)&Cout[(size_t)rr0 * NC + cc]       = v0;
                *(float2*)&Cout[(size_t)(rr0 + 8) * NC + cc] = v1;
            }
        return;
    }

    // ---- fused segment epilogue (whole CTA in one 128-col segment) ----
    auto store_seg = [&](int r, int cg, float va, float vb) {
        if (n0 < 2048) {
            *(float2*)&g_x[(size_t)r * D_INNER + cg] = make_float2(va, vb);
        } else if (n0 < 4096) {
            *(float2*)&g_zsil[(size_t)r * D_INNER + (cg - 2048)] = make_float2(silu_(va), silu_(vb));
        } else if (n0 < 4224) {
            *(float2*)&g_B[(size_t)r * D_STATE + (cg - 4096)] = make_float2(va, vb);
        } else if (n0 < 4352) {
            *(float2*)&g_C[(size_t)r * D_STATE + (cg - 4224)] = make_float2(va, vb);
        } else {
            int h = cg - 4352;
            float d0 = sp_(va), d1 = sp_(vb);
            *(float2*)&g_dtp[(size_t)r * HEADS + h] = make_float2(d0, d1);
            float2 dc = make_float2(expf(d0 * (-expf(A_log[h]))),
                                    expf(d1 * (-expf(A_log[h + 1]))));
            *(float2*)&g_decay[(size_t)r * HEADS + h] = dc;
        }
    };
    #pragma unroll
    for (int mt = 0; mt < 4; ++mt)
        #pragma unroll
        for (int nt = 0; nt < 8; ++nt) {
            const int rr0 = rbase + mt * 16;
            const int cc  = cbase + nt * 8;
            store_seg(rr0,     cc, acc[mt][nt][0], acc[mt][nt][1]);
            store_seg(rr0 + 8, cc, acc[mt][nt][2], acc[mt][nt][3]);
        }
}

// ---------------- conv + silu: 4 timesteps per thread -------------------------
__global__ void __launch_bounds__(256) conv_dtx_kernel(const float* __restrict__ conv_w,
                                                       const float* __restrict__ conv_b) {
    const int idx = blockIdx.x * 256 + threadIdx.x;
    const int c  = idx & (D_INNER - 1);
    const int r  = idx >> 11;
    const int bt0 = r << 2;
    const int t0  = bt0 & (SEQ - 1);
    const int h = c >> 1;

    const float w0 = conv_w[c * 4 + 0];
    const float w1 = conv_w[c * 4 + 1];
    const float w2 = conv_w[c * 4 + 2];
    const float w3 = conv_w[c * 4 + 3];
    const float bias = conv_b[c];

    float x[7];
    #pragma unroll
    for (int i = 0; i < 7; ++i) {
        int tt = t0 - 3 + i;
        x[i] = (tt >= 0) ? g_x[(size_t)(bt0 - 3 + i) * D_INNER + c] : 0.f;
    }

    #pragma unroll
    for (int j = 0; j < 4; ++j) {
        const int bt = bt0 + j;
        float acc = bias + w0 * x[j] + w1 * x[j+1] + w2 * x[j+2] + w3 * x[j+3];
        g_dtx[(size_t)bt * D_INNER + c] = g_dtp[(size_t)bt * HEADS + h] * silu_(acc);
    }
}

// ---------------- SSM scan (R12 single-kernel version) ------------------------
__device__ __forceinline__ unsigned long long pk2(float x, float y) {
    unsigned long long r;
    asm("mov.b64 %0, {%1, %2};" : "=l"(r) : "f"(x), "f"(y));
    return r;
}
__device__ __forceinline__ void upk2(unsigned long long v, float& x, float& y) {
    asm("mov.b64 {%0, %1}, %2;" : "=f"(x), "=f"(y) : "l"(v));
}
__device__ __forceinline__ unsigned long long ffma2_(unsigned long long a,
                                                     unsigned long long b,
                                                     unsigned long long c) {
    unsigned long long d;
    asm("fma.rn.f32x2 %0, %1, %2, %3;" : "=l"(d) : "l"(a), "l"(b), "l"(c));
    return d;
}
__device__ __forceinline__ unsigned long long fmul2_(unsigned long long a,
                                                     unsigned long long b) {
    unsigned long long d;
    asm("mul.rn.f32x2 %0, %1, %2;" : "=l"(d) : "l"(a), "l"(b));
    return d;
}

#define CHUNK 32
__global__ void __launch_bounds__(256, 1) scan_kernel() {
    __shared__ float sB[CHUNK][128];
    __shared__ float sC[CHUNK][128];
    __shared__ float sDec[CHUNK][16];
    __shared__ float sKx[CHUNK][32];
    __shared__ float sZ[CHUNK][32];

    const int tid = threadIdx.x;
    const int warp = tid >> 5, lane = tid & 31;
    const int batch = blockIdx.x >> 6;
    const int hbase = (blockIdx.x & 63) << 4;
    const int lhA = warp << 1;
    const int ni = lane << 2;

    unsigned long long a00 = 0, a01 = 0, a10 = 0, a11 = 0;
    unsigned long long b00 = 0, b01 = 0, b10 = 0, b11 = 0;

    const int sel = lane >> 3;
    const bool writer = (lane & 7) == 0;
    const int zloc = (lhA << 1) + sel;
    const int col = (hbase << 1) + zloc;

    for (int ch = 0; ch < SEQ / CHUNK; ++ch) {
        const size_t rowb = (size_t)(batch * SEQ + ch * CHUNK);
        __syncthreads();
        {
            #pragma unroll
            for (int i = tid; i < CHUNK * 32; i += 256) {
                int st = i >> 5, j = (i & 31) << 2;
                *(float4*)&sB[st][j] = *(const float4*)(g_B + (rowb + st) * D_STATE + j);
                *(float4*)&sC[st][j] = *(const float4*)(g_C + (rowb + st) * D_STATE + j);
            }
            #pragma unroll
            for (int i = tid; i < CHUNK * 16; i += 256) {
                int st = i >> 4, h = i & 15;
                sDec[st][h] = g_decay[(rowb + st) * HEADS + hbase + h];
            }
            #pragma unroll
            for (int i = tid; i < CHUNK * 32; i += 256) {
                int st = i >> 5, j = i & 31;
                size_t gi = (rowb + st) * D_INNER + ((size_t)hbase << 1) + j;
                sKx[st][j] = g_dtx[gi];
                sZ[st][j]  = g_zsil[gi];
            }
        }
        __syncthreads();

        #pragma unroll 2
        for (int tl = 0; tl < CHUNK; ++tl) {
            unsigned long long B01 = *(const unsigned long long*)&sB[tl][ni];
            unsigned long long B23 = *(const unsigned long long*)&sB[tl][ni + 2];
            unsigned long long C01 = *(const unsigned long long*)&sC[tl][ni];
            unsigned long long C23 = *(const unsigned long long*)&sC[tl][ni + 2];

            float decA = sDec[tl][lhA];
            float2 kxA = *(const float2*)&sKx[tl][lhA << 1];
            unsigned long long dA  = pk2(decA, decA);
            unsigned long long kA0 = pk2(kxA.x, kxA.x);
            unsigned long long kA1 = pk2(kxA.y, kxA.y);
            a00 = ffma2_(dA, a00, fmul2_(kA0, B01));
            a01 = ffma2_(dA, a01, fmul2_(kA0, B23));
            a10 = ffma2_(dA, a10, fmul2_(kA1, B01));
            a11 = ffma2_(dA, a11, fmul2_(kA1, B23));

            float decB = sDec[tl][lhA + 1];
            float2 kxB = *(const float2*)&sKx[tl][(lhA << 1) + 2];
            unsigned long long dB  = pk2(decB, decB);
            unsigned long long kB0 = pk2(kxB.x, kxB.x);
            unsigned long long kB1 = pk2(kxB.y, kxB.y);
            b00 = ffma2_(dB, b00, fmul2_(kB0, B01));
            b01 = ffma2_(dB, b01, fmul2_(kB0, B23));
            b10 = ffma2_(dB, b10, fmul2_(kB1, B01));
            b11 = ffma2_(dB, b11, fmul2_(kB1, B23));

            unsigned long long dp;
            float fx, fy;
            dp = ffma2_(a01, C23, fmul2_(a00, C01)); upk2(dp, fx, fy); float y0 = fx + fy;
            dp = ffma2_(a11, C23, fmul2_(a10, C01)); upk2(dp, fx, fy); float y1 = fx + fy;
            dp = ffma2_(b01, C23, fmul2_(b00, C01)); upk2(dp, fx, fy); float y2 = fx + fy;
            dp = ffma2_(b11, C23, fmul2_(b10, C01)); upk2(dp, fx, fy); float y3 = fx + fy;

            float t0v = (lane < 16) ? y2 : y0;
            float u0 = __shfl_xor_sync(0xffffffffu, t0v, 16);
            if (lane < 16) y0 += u0; else y2 += u0;
            float t1v = (lane < 16) ? y3 : y1;
            float u1 = __shfl_xor_sync(0xffffffffu, t1v, 16);
            if (lane < 16) y1 += u1; else y3 += u1;
            float v0 = (lane < 16) ? y0 : y2;
            float v1 = (lane < 16) ? y1 : y3;
            float tv = (lane & 8) ? v0 : v1;
            float uv = __shfl_xor_sync(0xffffffffu, tv, 8);
            if (lane & 8) v1 += uv; else v0 += uv;
            float v = (lane & 8) ? v1 : v0;
            v += __shfl_xor_sync(0xffffffffu, v, 4);
            v += __shfl_xor_sync(0xffffffffu, v, 2);
            v += __shfl_xor_sync(0xffffffffu, v, 1);

            if (writer) {
                float yv = v * sZ[tl][zloc];
                g_Ay[(rowb + tl) * D_INNER + col] = __float2half_rn(yv);
            }
        }
    }
}

// ---------------- launch ------------------------------------------------------
extern "C" void kernel_launch(void* const* d_in, const int* in_sizes, int n_in,
                              void* d_out, int out_size) {
    const float* u      = (const float*)d_in[0];
    const float* W_in   = (const float*)d_in[1];
    const float* conv_w = (const float*)d_in[2];
    const float* conv_b = (const float*)d_in[3];
    const float* W_out  = (const float*)d_in[4];
    const float* ln_g   = (const float*)d_in[5];
    const float* ln_b   = (const float*)d_in[6];
    const float* A_log  = (const float*)d_in[7];
    float* out = (float*)d_out;

    cudaFuncSetAttribute(gemm_mma<0>, cudaFuncAttributeMaxDynamicSharedMemorySize, GEMM_SMEM);
    cudaFuncSetAttribute(gemm_mma<1>, cudaFuncAttributeMaxDynamicSharedMemorySize, GEMM_SMEM);

    ln_kernel<<<NTOK, 256>>>(u, ln_g, ln_b);
    wconv_kernel<0><<<dim3(PROJ_OUT / 32, D_MODEL / 32), dim3(32, 32)>>>(W_in);
    gemm_mma<0><<<dim3(PROJ_OUT / 128, NTOK / 256), 256, GEMM_SMEM>>>(nullptr, nullptr, A_log);
    conv_dtx_kernel<<<(NTOK * D_INNER / 4) / 256, 256>>>(conv_w, conv_b);
    scan_kernel<<<128, 256>>>();
    wconv_kernel<1><<<dim3(D_MODEL / 32, D_INNER / 32), dim3(32, 32)>>>(W_out);
    gemm_mma<1><<<dim3(D_MODEL / 128, NTOK / 256), 256, GEMM_SMEM>>>(u, out, nullptr);
}

// round 17
// speedup vs baseline: 1.1460x; 1.1460x over previous
#include <cuda_runtime.h>
#include <cuda_fp16.h>
#include <cstdint>

#define D_MODEL  1024
#define D_STATE  128
#define D_INNER  2048
#define HEADS    1024
#define PROJ_OUT 5376
#define BATCH    2
#define SEQ      2048
#define NTOK     (BATCH*SEQ)   // 4096

// ---------------- scratch (device globals) -----------------------------------
__device__ float g_x    [(size_t)NTOK * D_INNER];   // x columns (pre-conv)
__device__ float g_zsil [(size_t)NTOK * D_INNER];   // silu(z)
__device__ float g_B    [(size_t)NTOK * D_STATE];
__device__ float g_C    [(size_t)NTOK * D_STATE];
__device__ float g_dtp  [(size_t)NTOK * HEADS];     // softplus(dt)
__device__ float g_decay[(size_t)NTOK * HEADS];     // exp(dtp * -exp(A_log))
__device__ float g_dtx  [(size_t)NTOK * D_INNER];   // dtp * silu(conv(x))
__device__ __half g_Ain [(size_t)NTOK * D_MODEL];      // fp16(ln(u))
__device__ __half g_Bin [(size_t)PROJ_OUT * D_MODEL];  // fp16(W_in^T)
__device__ __half g_Ay  [(size_t)NTOK * D_INNER];      // fp16(y*silu(z))
__device__ __half g_Bout[(size_t)D_MODEL * D_INNER];   // fp16(W_out^T)

// ---------------- helpers -----------------------------------------------------
struct alignas(8) hf4 { __half v[4]; };

__device__ __forceinline__ uint32_t smem_u32(const void* p) {
    uint32_t a;
    asm("{ .reg .u64 t; cvta.to.shared.u64 t, %1; cvt.u32.u64 %0, t; }" : "=r"(a) : "l"(p));
    return a;
}
__device__ __forceinline__ void cp16(uint32_t s, const void* g) {
    asm volatile("cp.async.cg.shared.global [%0], [%1], 16;" :: "r"(s), "l"(g) : "memory");
}
#define CP_COMMIT() asm volatile("cp.async.commit_group;" ::: "memory")

__device__ __forceinline__ void ldsm_x4(uint32_t& r0, uint32_t& r1, uint32_t& r2, uint32_t& r3,
                                        uint32_t addr) {
    asm volatile("ldmatrix.sync.aligned.m8n8.x4.shared.b16 {%0,%1,%2,%3}, [%4];"
                 : "=r"(r0), "=r"(r1), "=r"(r2), "=r"(r3) : "r"(addr));
}
__device__ __forceinline__ void mma16816(float& d0, float& d1, float& d2, float& d3,
                                         uint32_t a0, uint32_t a1, uint32_t a2, uint32_t a3,
                                         uint32_t b0, uint32_t b1) {
    asm volatile("mma.sync.aligned.m16n8k16.row.col.f32.f16.f16.f32 "
                 "{%0,%1,%2,%3}, {%4,%5,%6,%7}, {%8,%9}, {%0,%1,%2,%3};"
                 : "+f"(d0), "+f"(d1), "+f"(d2), "+f"(d3)
                 : "r"(a0), "r"(a1), "r"(a2), "r"(a3), "r"(b0), "r"(b1));
}
// smem tile byte offset, row-major [128][32] fp16 with XOR swizzle for LDSM
__device__ __forceinline__ uint32_t swz(uint32_t row, uint32_t k) {
    uint32_t chunk = (k >> 3) ^ ((row >> 1) & 3);
    return row * 64 + chunk * 16 + (k & 7) * 2;
}
__device__ __forceinline__ float sp_(float v) {           // softplus
    return (v > 20.f) ? v : log1pf(expf(v));
}
__device__ __forceinline__ float silu_(float v) {
    return v / (1.f + expf(-v));
}

// ---------------- 1. LayerNorm -> fp16 A --------------------------------------
__global__ void __launch_bounds__(256) ln_kernel(const float* __restrict__ u,
                                                 const float* __restrict__ g,
                                                 const float* __restrict__ b) {
    __shared__ float sS[8], sQ[8], sMV[2];
    const int row = blockIdx.x;
    const int tid = threadIdx.x;
    const int warp = tid >> 5, lane = tid & 31;

    float4 v = *((const float4*)(u + (size_t)row * D_MODEL) + tid);
    float s = v.x + v.y + v.z + v.w;
    float q = v.x*v.x + v.y*v.y + v.z*v.z + v.w*v.w;
    #pragma unroll
    for (int off = 16; off > 0; off >>= 1) {
        s += __shfl_xor_sync(0xffffffffu, s, off);
        q += __shfl_xor_sync(0xffffffffu, q, off);
    }
    if (lane == 0) { sS[warp] = s; sQ[warp] = q; }
    __syncthreads();
    if (tid == 0) {
        float S = 0.f, Q = 0.f;
        #pragma unroll
        for (int i = 0; i < 8; ++i) { S += sS[i]; Q += sQ[i]; }
        float mean = S * (1.0f / D_MODEL);
        float var  = Q * (1.0f / D_MODEL) - mean * mean;
        sMV[0] = mean;
        sMV[1] = rsqrtf(var + 1e-5f);
    }
    __syncthreads();
    const float mean = sMV[0], rstd = sMV[1];
    float4 gg = ((const float4*)g)[tid];
    float4 bb = ((const float4*)b)[tid];
    hf4 H;
    H.v[0] = __float2half_rn((v.x - mean) * rstd * gg.x + bb.x);
    H.v[1] = __float2half_rn((v.y - mean) * rstd * gg.y + bb.y);
    H.v[2] = __float2half_rn((v.z - mean) * rstd * gg.z + bb.z);
    H.v[3] = __float2half_rn((v.w - mean) * rstd * gg.w + bb.w);
    *(hf4*)(g_Ain + (size_t)row * D_MODEL + tid * 4) = H;
}

// ---------------- weight transpose fp16: W[K,N] -> B[N,K] --------------------
template<int PHASE>
__global__ void wconv_kernel(const float* __restrict__ W) {
    constexpr int K = PHASE ? D_INNER : D_MODEL;
    constexpr int N = PHASE ? D_MODEL : PROJ_OUT;
    __half* __restrict__ Bo = PHASE ? g_Bout : g_Bin;

    __shared__ float t[32][33];
    const int tx = threadIdx.x, ty = threadIdx.y;
    const int n0 = blockIdx.x * 32, k0 = blockIdx.y * 32;
    t[ty][tx] = W[(size_t)(k0 + ty) * N + n0 + tx];
    __syncthreads();
    Bo[(size_t)(n0 + ty) * K + k0 + tx] = __float2half_rn(t[tx][ty]);
}

// ---------------- fp16 mma.sync GEMM (128x128x32, 3-stage, ldmatrix) ---------
// __launch_bounds__(256,2): cap regs at 128 so 2 CTAs co-reside per SM
// (96 KB smem, 16 warps) for latency coverage.
// PHASE 0: g_Ain @ g_Bin^T  -> fused segment epilogue (compact buffers)
// PHASE 1: g_Ay @ g_Bout^T + u -> out fp32
template<int PHASE>
__global__ void __launch_bounds__(256, 2) gemm_mma(const float* __restrict__ R,
                                                   float* __restrict__ Cout,
                                                   const float* __restrict__ A_log) {
    constexpr int TK = PHASE ? D_INNER : D_MODEL;
    constexpr int NC = PHASE ? D_MODEL : PROJ_OUT;
    constexpr int NITER = TK / 32;

    const __half* Asrc = PHASE ? g_Ay  : g_Ain;
    const __half* Bsrc = PHASE ? g_Bout : g_Bin;

    __shared__ char smemraw[3 * 16384];
    const uint32_t sb = smem_u32(smemraw);

    const int tid = threadIdx.x;
    const int wid = tid >> 5, lane = tid & 31;
    const int wm = wid & 1, wn = wid >> 1;
    const int m0 = blockIdx.y * 128, n0 = blockIdx.x * 128;
    const __half* Ag = Asrc + (size_t)m0 * TK;
    const __half* Bg = Bsrc + (size_t)n0 * TK;

    auto load_stage = [&](int it, int st) {
        const int k0 = it * 32;
        const uint32_t base = sb + st * 16384;
        #pragma unroll
        for (int i = 0; i < 2; ++i) {
            const int idx = tid + i * 256;
            const int row = idx >> 2, ch = idx & 3;
            const uint32_t off = swz(row, ch * 8);
            cp16(base        + off, Ag + (size_t)row * TK + k0 + ch * 8);
            cp16(base + 8192 + off, Bg + (size_t)row * TK + k0 + ch * 8);
        }
    };

    float acc[4][4][4];
    #pragma unroll
    for (int mt = 0; mt < 4; ++mt)
        #pragma unroll
        for (int nt = 0; nt < 4; ++nt)
            #pragma unroll
            for (int r = 0; r < 4; ++r) acc[mt][nt][r] = 0.f;

    load_stage(0, 0); CP_COMMIT();
    load_stage(1, 1); CP_COMMIT();

    const uint32_t a_row = wm * 64 + (lane & 15);
    const uint32_t a_k   = (lane >> 4) * 8;
    const uint32_t b_row = wn * 32 + ((lane >> 4) & 1) * 8 + (lane & 7);
    const uint32_t b_k   = ((lane >> 3) & 1) * 8;

    int st = 0;
    for (int it = 0; it < NITER; ++it) {
        asm volatile("cp.async.wait_group 1;" ::: "memory");
        __syncthreads();
        if (it + 2 < NITER) load_stage(it + 2, (st + 2) % 3);
        CP_COMMIT();

        const uint32_t abase = sb + st * 16384;
        const uint32_t bbase = abase + 8192;
        #pragma unroll
        for (int ks = 0; ks < 2; ++ks) {
            uint32_t a[4][4], b[4][2];
            #pragma unroll
            for (int mt = 0; mt < 4; ++mt)
                ldsm_x4(a[mt][0], a[mt][1], a[mt][2], a[mt][3],
                        abase + swz(a_row + mt * 16, ks * 16 + a_k));
            #pragma unroll
            for (int nt2 = 0; nt2 < 2; ++nt2)
                ldsm_x4(b[nt2*2][0], b[nt2*2][1], b[nt2*2+1][0], b[nt2*2+1][1],
                        bbase + swz(b_row + nt2 * 16, ks * 16 + b_k));
            #pragma unroll
            for (int mt = 0; mt < 4; ++mt)
                #pragma unroll
                for (int nt = 0; nt < 4; ++nt)
                    mma16816(acc[mt][nt][0], acc[mt][nt][1], acc[mt][nt][2], acc[mt][nt][3],
                             a[mt][0], a[mt][1], a[mt][2], a[mt][3], b[nt][0], b[nt][1]);
        }
        st = (st + 1) % 3;
    }

    const int rbase = m0 + wm * 64 + (lane >> 2);
    const int cbase = n0 + wn * 32 + 2 * (lane & 3);

    if (PHASE == 1) {
        #pragma unroll
        for (int mt = 0; mt < 4; ++mt)
            #pragma unroll
            for (int nt = 0; nt < 4; ++nt) {
                const int rr0 = rbase + mt * 16;
                const int cc  = cbase + nt * 8;
                float2 v0 = make_float2(acc[mt][nt][0], acc[mt][nt][1]);
                float2 v1 = make_float2(acc[mt][nt][2], acc[mt][nt][3]);
                float2 r0 = *(const float2*)&R[(size_t)rr0 * NC + cc];
                float2 r1 = *(const float2*)&R[(size_t)(rr0 + 8) * NC + cc];
                v0.x += r0.x; v0.y += r0.y;
                v1.x += r1.x; v1.y += r1.y;
                *(float2*)&Cout[(size_t)rr0 * NC + cc]       = v0;
                *(float2*)&Cout[(size_t)(rr0 + 8) * NC + cc] = v1;
            }
        return;
    }

    // ---- fused segment epilogue (whole CTA in one 128-col segment) ----
    auto store_seg = [&](int r, int cg, float va, float vb) {
        if (n0 < 2048) {
            *(float2*)&g_x[(size_t)r * D_INNER + cg] = make_float2(va, vb);
        } else if (n0 < 4096) {
            *(float2*)&g_zsil[(size_t)r * D_INNER + (cg - 2048)] = make_float2(silu_(va), silu_(vb));
        } else if (n0 < 4224) {
            *(float2*)&g_B[(size_t)r * D_STATE + (cg - 4096)] = make_float2(va, vb);
        } else if (n0 < 4352) {
            *(float2*)&g_C[(size_t)r * D_STATE + (cg - 4224)] = make_float2(va, vb);
        } else {
            int h = cg - 4352;
            float d0 = sp_(va), d1 = sp_(vb);
            *(float2*)&g_dtp[(size_t)r * HEADS + h] = make_float2(d0, d1);
            float2 dc = make_float2(expf(d0 * (-expf(A_log[h]))),
                                    expf(d1 * (-expf(A_log[h + 1]))));
            *(float2*)&g_decay[(size_t)r * HEADS + h] = dc;
        }
    };
    #pragma unroll
    for (int mt = 0; mt < 4; ++mt)
        #pragma unroll
        for (int nt = 0; nt < 4; ++nt) {
            const int rr0 = rbase + mt * 16;
            const int cc  = cbase + nt * 8;
            store_seg(rr0,     cc, acc[mt][nt][0], acc[mt][nt][1]);
            store_seg(rr0 + 8, cc, acc[mt][nt][2], acc[mt][nt][3]);
        }
}

// ---------------- conv + silu: 4 timesteps per thread -------------------------
__global__ void __launch_bounds__(256) conv_dtx_kernel(const float* __restrict__ conv_w,
                                                       const float* __restrict__ conv_b) {
    const int idx = blockIdx.x * 256 + threadIdx.x;
    const int c  = idx & (D_INNER - 1);
    const int r  = idx >> 11;
    const int bt0 = r << 2;
    const int t0  = bt0 & (SEQ - 1);
    const int h = c >> 1;

    const float w0 = conv_w[c * 4 + 0];
    const float w1 = conv_w[c * 4 + 1];
    const float w2 = conv_w[c * 4 + 2];
    const float w3 = conv_w[c * 4 + 3];
    const float bias = conv_b[c];

    float x[7];
    #pragma unroll
    for (int i = 0; i < 7; ++i) {
        int tt = t0 - 3 + i;
        x[i] = (tt >= 0) ? g_x[(size_t)(bt0 - 3 + i) * D_INNER + c] : 0.f;
    }

    #pragma unroll
    for (int j = 0; j < 4; ++j) {
        const int bt = bt0 + j;
        float acc = bias + w0 * x[j] + w1 * x[j+1] + w2 * x[j+2] + w3 * x[j+3];
        g_dtx[(size_t)bt * D_INNER + c] = g_dtp[(size_t)bt * HEADS + h] * silu_(acc);
    }
}

// ---------------- SSM scan (R12 single-kernel version) ------------------------
__device__ __forceinline__ unsigned long long pk2(float x, float y) {
    unsigned long long r;
    asm("mov.b64 %0, {%1, %2};" : "=l"(r) : "f"(x), "f"(y));
    return r;
}
__device__ __forceinline__ void upk2(unsigned long long v, float& x, float& y) {
    asm("mov.b64 {%0, %1}, %2;" : "=f"(x), "=f"(y) : "l"(v));
}
__device__ __forceinline__ unsigned long long ffma2_(unsigned long long a,
                                                     unsigned long long b,
                                                     unsigned long long c) {
    unsigned long long d;
    asm("fma.rn.f32x2 %0, %1, %2, %3;" : "=l"(d) : "l"(a), "l"(b), "l"(c));
    return d;
}
__device__ __forceinline__ unsigned long long fmul2_(unsigned long long a,
                                                     unsigned long long b) {
    unsigned long long d;
    asm("mul.rn.f32x2 %0, %1, %2;" : "=l"(d) : "l"(a), "l"(b));
    return d;
}

#define CHUNK 32
__global__ void __launch_bounds__(256, 1) scan_kernel() {
    __shared__ float sB[CHUNK][128];
    __shared__ float sC[CHUNK][128];
    __shared__ float sDec[CHUNK][16];
    __shared__ float sKx[CHUNK][32];
    __shared__ float sZ[CHUNK][32];

    const int tid = threadIdx.x;
    const int warp = tid >> 5, lane = tid & 31;
    const int batch = blockIdx.x >> 6;
    const int hbase = (blockIdx.x & 63) << 4;
    const int lhA = warp << 1;
    const int ni = lane << 2;

    unsigned long long a00 = 0, a01 = 0, a10 = 0, a11 = 0;
    unsigned long long b00 = 0, b01 = 0, b10 = 0, b11 = 0;

    const int sel = lane >> 3;
    const bool writer = (lane & 7) == 0;
    const int zloc = (lhA << 1) + sel;
    const int col = (hbase << 1) + zloc;

    for (int ch = 0; ch < SEQ / CHUNK; ++ch) {
        const size_t rowb = (size_t)(batch * SEQ + ch * CHUNK);
        __syncthreads();
        {
            #pragma unroll
            for (int i = tid; i < CHUNK * 32; i += 256) {
                int st = i >> 5, j = (i & 31) << 2;
                *(float4*)&sB[st][j] = *(const float4*)(g_B + (rowb + st) * D_STATE + j);
                *(float4*)&sC[st][j] = *(const float4*)(g_C + (rowb + st) * D_STATE + j);
            }
            #pragma unroll
            for (int i = tid; i < CHUNK * 16; i += 256) {
                int st = i >> 4, h = i & 15;
                sDec[st][h] = g_decay[(rowb + st) * HEADS + hbase + h];
            }
            #pragma unroll
            for (int i = tid; i < CHUNK * 32; i += 256) {
                int st = i >> 5, j = i & 31;
                size_t gi = (rowb + st) * D_INNER + ((size_t)hbase << 1) + j;
                sKx[st][j] = g_dtx[gi];
                sZ[st][j]  = g_zsil[gi];
            }
        }
        __syncthreads();

        #pragma unroll 2
        for (int tl = 0; tl < CHUNK; ++tl) {
            unsigned long long B01 = *(const unsigned long long*)&sB[tl][ni];
            unsigned long long B23 = *(const unsigned long long*)&sB[tl][ni + 2];
            unsigned long long C01 = *(const unsigned long long*)&sC[tl][ni];
            unsigned long long C23 = *(const unsigned long long*)&sC[tl][ni + 2];

            float decA = sDec[tl][lhA];
            float2 kxA = *(const float2*)&sKx[tl][lhA << 1];
            unsigned long long dA  = pk2(decA, decA);
            unsigned long long kA0 = pk2(kxA.x, kxA.x);
            unsigned long long kA1 = pk2(kxA.y, kxA.y);
            a00 = ffma2_(dA, a00, fmul2_(kA0, B01));
            a01 = ffma2_(dA, a01, fmul2_(kA0, B23));
            a10 = ffma2_(dA, a10, fmul2_(kA1, B01));
            a11 = ffma2_(dA, a11, fmul2_(kA1, B23));

            float decB = sDec[tl][lhA + 1];
            float2 kxB = *(const float2*)&sKx[tl][(lhA << 1) + 2];
            unsigned long long dB  = pk2(decB, decB);
            unsigned long long kB0 = pk2(kxB.x, kxB.x);
            unsigned long long kB1 = pk2(kxB.y, kxB.y);
            b00 = ffma2_(dB, b00, fmul2_(kB0, B01));
            b01 = ffma2_(dB, b01, fmul2_(kB0, B23));
            b10 = ffma2_(dB, b10, fmul2_(kB1, B01));
            b11 = ffma2_(dB, b11, fmul2_(kB1, B23));

            unsigned long long dp;
            float fx, fy;
            dp = ffma2_(a01, C23, fmul2_(a00, C01)); upk2(dp, fx, fy); float y0 = fx + fy;
            dp = ffma2_(a11, C23, fmul2_(a10, C01)); upk2(dp, fx, fy); float y1 = fx + fy;
            dp = ffma2_(b01, C23, fmul2_(b00, C01)); upk2(dp, fx, fy); float y2 = fx + fy;
            dp = ffma2_(b11, C23, fmul2_(b10, C01)); upk2(dp, fx, fy); float y3 = fx + fy;

            float t0v = (lane < 16) ? y2 : y0;
            float u0 = __shfl_xor_sync(0xffffffffu, t0v, 16);
            if (lane < 16) y0 += u0; else y2 += u0;
            float t1v = (lane < 16) ? y3 : y1;
            float u1 = __shfl_xor_sync(0xffffffffu, t1v, 16);
            if (lane < 16) y1 += u1; else y3 += u1;
            float v0 = (lane < 16) ? y0 : y2;
            float v1 = (lane < 16) ? y1 : y3;
            float tv = (lane & 8) ? v0 : v1;
            float uv = __shfl_xor_sync(0xffffffffu, tv, 8);
            if (lane & 8) v1 += uv; else v0 += uv;
            float v = (lane & 8) ? v1 : v0;
            v += __shfl_xor_sync(0xffffffffu, v, 4);
            v += __shfl_xor_sync(0xffffffffu, v, 2);
            v += __shfl_xor_sync(0xffffffffu, v, 1);

            if (writer) {
                float yv = v * sZ[tl][zloc];
                g_Ay[(rowb + tl) * D_INNER + col] = __float2half_rn(yv);
            }
        }
    }
}

// ---------------- launch ------------------------------------------------------
extern "C" void kernel_launch(void* const* d_in, const int* in_sizes, int n_in,
                              void* d_out, int out_size) {
    const float* u      = (const float*)d_in[0];
    const float* W_in   = (const float*)d_in[1];
    const float* conv_w = (const float*)d_in[2];
    const float* conv_b = (const float*)d_in[3];
    const float* W_out  = (const float*)d_in[4];
    const float* ln_g   = (const float*)d_in[5];
    const float* ln_b   = (const float*)d_in[6];
    const float* A_log  = (const float*)d_in[7];
    float* out = (float*)d_out;

    ln_kernel<<<NTOK, 256>>>(u, ln_g, ln_b);
    wconv_kernel<0><<<dim3(PROJ_OUT / 32, D_MODEL / 32), dim3(32, 32)>>>(W_in);
    gemm_mma<0><<<dim3(PROJ_OUT / 128, NTOK / 128), 256>>>(nullptr, nullptr, A_log);
    conv_dtx_kernel<<<(NTOK * D_INNER / 4) / 256, 256>>>(conv_w, conv_b);
    scan_kernel<<<128, 256>>>();
    wconv_kernel<1><<<dim3(D_MODEL / 32, D_INNER / 32), dim3(32, 32)>>>(W_out);
    gemm_mma<1><<<dim3(D_MODEL / 128, NTOK / 128), 256>>>(u, out, nullptr);
}